// round 15
// baseline (speedup 1.0000x reference)
#include <cuda_runtime.h>
#include <cuda_bf16.h>
#include <math.h>
#include <stdint.h>

#define DMODEL 1024
#define NHEADS 16
#define DHEAD  64
#define DMLP   4096
#define BATCH  2
#define SEQ    2048
#define NTOK   (BATCH*SEQ)      /* 4096 */
#define QKVW   (3*DMODEL)       /* 3072 */
#define LNEPS  1e-5f

// ---------------- scratch (static device globals) ----------------------------------------
__device__ __nv_bfloat16 g_xn  [(size_t)NTOK*DMODEL];
__device__ __nv_bfloat16 g_wqkv[(size_t)DMODEL*QKVW];   // [K=1024][N=3072]
__device__ float         g_bqkv[QKVW];
__device__ __nv_bfloat16 g_qkv [(size_t)NTOK*QKVW];
__device__ __nv_bfloat16 g_z   [(size_t)NTOK*DMODEL];
__device__ float         g_mid [(size_t)NTOK*DMODEL];
__device__ __nv_bfloat16 g_hid [(size_t)NTOK*DMLP];
__device__ __nv_bfloat16 g_wo  [(size_t)DMODEL*DMODEL]; // [K][N]
__device__ __nv_bfloat16 g_win [(size_t)DMODEL*DMLP];   // [K][N]
__device__ __nv_bfloat16 g_wout[(size_t)DMLP*DMODEL];   // [K][N]

// ---------------- side streams for graph-parallel preamble (created pre-main) -------------
namespace {
struct HxStreams {
    cudaStream_t s1, s2;
    cudaEvent_t  e0, e1, e2;
    HxStreams() {
        cudaStreamCreateWithFlags(&s1, cudaStreamNonBlocking);
        cudaStreamCreateWithFlags(&s2, cudaStreamNonBlocking);
        cudaEventCreateWithFlags(&e0, cudaEventDisableTiming);
        cudaEventCreateWithFlags(&e1, cudaEventDisableTiming);
        cudaEventCreateWithFlags(&e2, cudaEventDisableTiming);
    }
};
HxStreams g_hx;
}

// ---------------- weight repack / convert -------------------------------------------------
// vectorized: one thread handles 4 consecutive k-elements (float4 -> 4x bf16)
__global__ void __launch_bounds__(256) pack_wqkv_kernel(
    const float* __restrict__ wq, const float* __restrict__ wk, const float* __restrict__ wv)
{
    int idx = blockIdx.x * 256 + threadIdx.x;          // [0, 3*1024*1024/4)
    int which = idx >> 18;
    int r4 = idx & 0x3FFFF;                            // 4-element chunk within one weight
    const float* src = (which == 0) ? wq : (which == 1) ? wk : wv;
    float4 v = *(const float4*)(src + (size_t)r4 * 4);
    int h  = r4 >> 14;
    int d  = (r4 >> 4) & 1023;
    int k0 = (r4 & 15) * 4;
    __nv_bfloat162 p0 = __floats2bfloat162_rn(v.x, v.y);
    __nv_bfloat162 p1 = __floats2bfloat162_rn(v.z, v.w);
    uint2 st;
    st.x = *(uint32_t*)&p0;
    st.y = *(uint32_t*)&p1;
    *(uint2*)(g_wqkv + (size_t)d * QKVW + which * DMODEL + h * DHEAD + k0) = st;
}

__global__ void __launch_bounds__(256) conv_bf16_kernel(
    const float4* __restrict__ s, uint2* __restrict__ d, int n4)
{
    int i = blockIdx.x * 256 + threadIdx.x;
    if (i < n4) {
        float4 v = s[i];
        __nv_bfloat162 a = __floats2bfloat162_rn(v.x, v.y);
        __nv_bfloat162 b = __floats2bfloat162_rn(v.z, v.w);
        uint2 o;
        o.x = *(uint32_t*)&a;
        o.y = *(uint32_t*)&b;
        d[i] = o;
    }
}

// ---------------- LayerNorm (fp32 in, bf16 out) -------------------------------------------
__global__ void __launch_bounds__(256) ln_kernel(
    const float* __restrict__ x, const float* __restrict__ w, const float* __restrict__ bb,
    __nv_bfloat16* __restrict__ y)
{
    __shared__ float red[18];
    int t = threadIdx.x;
    size_t off = (size_t)blockIdx.x * DMODEL;
    float4 v = *(const float4*)(x + off + t * 4);
    float s  = v.x + v.y + v.z + v.w;
    float sq = v.x*v.x + v.y*v.y + v.z*v.z + v.w*v.w;
    #pragma unroll
    for (int o = 16; o > 0; o >>= 1) {
        s  += __shfl_xor_sync(0xffffffffu, s,  o);
        sq += __shfl_xor_sync(0xffffffffu, sq, o);
    }
    if ((t & 31) == 0) { red[t >> 5] = s; red[8 + (t >> 5)] = sq; }
    __syncthreads();
    if (t == 0) {
        float ts = 0.f, tq = 0.f;
        #pragma unroll
        for (int i = 0; i < 8; i++) { ts += red[i]; tq += red[8 + i]; }
        float mean = ts * (1.f / DMODEL);
        float var  = tq * (1.f / DMODEL) - mean * mean;
        red[16] = mean;
        red[17] = rsqrtf(var + LNEPS);
    }
    __syncthreads();
    float mean = red[16], rstd = red[17];
    float4 w4 = *(const float4*)(w  + t * 4);
    float4 b4 = *(const float4*)(bb + t * 4);
    __nv_bfloat162 p0 = __floats2bfloat162_rn((v.x - mean) * rstd * w4.x + b4.x,
                                              (v.y - mean) * rstd * w4.y + b4.y);
    __nv_bfloat162 p1 = __floats2bfloat162_rn((v.z - mean) * rstd * w4.z + b4.z,
                                              (v.w - mean) * rstd * w4.w + b4.w);
    uint2 st;
    st.x = *(uint32_t*)&p0;
    st.y = *(uint32_t*)&p1;
    *(uint2*)(y + off + t * 4) = st;
}

// ---------------- common helpers ----------------------------------------------------------
__device__ __forceinline__ uint32_t s2u(const void* p) {
    return (uint32_t)__cvta_generic_to_shared(p);
}
__device__ __forceinline__ void mma_bf16(float* d, const uint32_t* a, uint32_t b0, uint32_t b1) {
    asm volatile(
        "mma.sync.aligned.m16n8k16.row.col.f32.bf16.bf16.f32 "
        "{%0,%1,%2,%3}, {%4,%5,%6,%7}, {%8,%9}, {%0,%1,%2,%3};\n"
        : "+f"(d[0]), "+f"(d[1]), "+f"(d[2]), "+f"(d[3])
        : "r"(a[0]), "r"(a[1]), "r"(a[2]), "r"(a[3]), "r"(b0), "r"(b1));
}
__device__ __forceinline__ void ldm_x4(uint32_t* r, uint32_t addr) {
    asm volatile("ldmatrix.sync.aligned.m8n8.x4.shared.b16 {%0,%1,%2,%3}, [%4];\n"
        : "=r"(r[0]), "=r"(r[1]), "=r"(r[2]), "=r"(r[3]) : "r"(addr));
}
__device__ __forceinline__ void ldm_x4t(uint32_t* r, uint32_t addr) {
    asm volatile("ldmatrix.sync.aligned.m8n8.x4.trans.shared.b16 {%0,%1,%2,%3}, [%4];\n"
        : "=r"(r[0]), "=r"(r[1]), "=r"(r[2]), "=r"(r[3]) : "r"(addr));
}

// ---------------- bf16 mma.sync GEMM: 4 warps, 64x64 warp tile, 4-stage, single-sync ------
__device__ __forceinline__ int a_off(int m, int kbyte) {
    int line = m >> 1;
    return (line * 128 + (m & 1) * 64 + kbyte) ^ ((line & 7) << 4);
}
__device__ __forceinline__ int b_off(int k, int nbyte) {
    return (k * 256 + nbyte) ^ ((k & 7) << 4);
}

#define GSTAGES 4

template<bool RELU, bool RES, bool OUTBF>
__global__ void __launch_bounds__(128, 3) bgemm_kernel(
    const __nv_bfloat16* __restrict__ A, const __nv_bfloat16* __restrict__ B,
    const float* __restrict__ bias, const float* __restrict__ Rp,
    void* __restrict__ Cv, int M, int N, int K)
{
    __shared__ __align__(128) unsigned char smem[GSTAGES * 16384];
    uint32_t base = s2u(smem);

    int tid  = threadIdx.x;
    int warp = tid >> 5, lane = tid & 31;
    int wm = warp >> 1, wn = warp & 1;
    int gr = lane >> 2, gc = lane & 3;

    const __nv_bfloat16* Ab = A + (size_t)blockIdx.y * 128 * K;
    const __nv_bfloat16* Bb = B + blockIdx.x * 128;

    int ar = tid >> 2, ac = tid & 3;
    int brr = tid >> 4, bcc = tid & 15;

    float acc[4][8][4];
    #pragma unroll
    for (int mi = 0; mi < 4; mi++)
        #pragma unroll
        for (int ni = 0; ni < 8; ni++)
            #pragma unroll
            for (int i = 0; i < 4; i++) acc[mi][ni][i] = 0.f;

    int T = K >> 5;

    #pragma unroll
    for (int s = 0; s < GSTAGES - 1; s++) {
        uint32_t as = base + s * 16384;
        uint32_t bs = as + 8192;
        int kt = s * 32;
        #pragma unroll
        for (int i = 0; i < 4; i++) {
            int r = ar + i * 32;
            asm volatile("cp.async.cg.shared.global [%0], [%1], 16;\n" ::
                "r"(as + a_off(r, ac * 16)), "l"(Ab + (size_t)r * K + kt + ac * 8));
        }
        #pragma unroll
        for (int i = 0; i < 4; i++) {
            int r = brr + i * 8;
            asm volatile("cp.async.cg.shared.global [%0], [%1], 16;\n" ::
                "r"(bs + b_off(r, bcc * 16)), "l"(Bb + (size_t)(kt + r) * N + bcc * 8));
        }
        asm volatile("cp.async.commit_group;\n");
    }

    for (int t = 0; t < T; t++) {
        asm volatile("cp.async.wait_group %0;\n" :: "n"(GSTAGES - 2));
        __syncthreads();

        if (t + GSTAGES - 1 < T) {
            int s  = (t + GSTAGES - 1) % GSTAGES;
            uint32_t was = base + s * 16384;
            uint32_t wbs = was + 8192;
            int kt = (t + GSTAGES - 1) * 32;
            #pragma unroll
            for (int i = 0; i < 4; i++) {
                int r = ar + i * 32;
                asm volatile("cp.async.cg.shared.global [%0], [%1], 16;\n" ::
                    "r"(was + a_off(r, ac * 16)), "l"(Ab + (size_t)r * K + kt + ac * 8));
            }
            #pragma unroll
            for (int i = 0; i < 4; i++) {
                int r = brr + i * 8;
                asm volatile("cp.async.cg.shared.global [%0], [%1], 16;\n" ::
                    "r"(wbs + b_off(r, bcc * 16)), "l"(Bb + (size_t)(kt + r) * N + bcc * 8));
            }
        }
        asm volatile("cp.async.commit_group;\n");

        uint32_t as = base + (t % GSTAGES) * 16384;
        uint32_t bs = as + 8192;

        #pragma unroll
        for (int ks = 0; ks < 2; ks++) {
            uint32_t af[4][4];
            #pragma unroll
            for (int mi = 0; mi < 4; mi++) {
                int m  = wm * 64 + mi * 16 + (lane & 15);
                int kb = ks * 32 + (lane >> 4) * 16;
                ldm_x4(af[mi], as + a_off(m, kb));
            }
            uint32_t bf[4][4];
            #pragma unroll
            for (int np = 0; np < 4; np++) {
                int k  = ks * 16 + (lane & 15);
                int nb = (wn * 64 + np * 16 + (lane >> 4) * 8) * 2;
                ldm_x4t(bf[np], bs + b_off(k, nb));
            }
            #pragma unroll
            for (int mi = 0; mi < 4; mi++)
                #pragma unroll
                for (int ni = 0; ni < 8; ni++)
                    mma_bf16(acc[mi][ni], af[mi], bf[ni >> 1][(ni & 1) * 2],
                             bf[ni >> 1][(ni & 1) * 2 + 1]);
        }
    }

    int Rm = blockIdx.y * 128 + wm * 64;
    int Rn = blockIdx.x * 128 + wn * 64;
    #pragma unroll
    for (int mi = 0; mi < 4; mi++) {
        #pragma unroll
        for (int ni = 0; ni < 8; ni++) {
            int col = Rn + ni * 8 + gc * 2;
            float2 bv = *(const float2*)&bias[col];
            #pragma unroll
            for (int hh = 0; hh < 2; hh++) {
                int row = Rm + mi * 16 + gr + hh * 8;
                size_t ro = (size_t)row * N + col;
                float2 cv;
                cv.x = acc[mi][ni][2 * hh + 0] + bv.x;
                cv.y = acc[mi][ni][2 * hh + 1] + bv.y;
                if (RES) {
                    float2 rv = *(const float2*)&Rp[ro];
                    cv.x += rv.x; cv.y += rv.y;
                }
                if (RELU) { cv.x = fmaxf(cv.x, 0.f); cv.y = fmaxf(cv.y, 0.f); }
                if (OUTBF) {
                    __nv_bfloat162 o = __floats2bfloat162_rn(cv.x, cv.y);
                    *(__nv_bfloat162*)((__nv_bfloat16*)Cv + ro) = o;
                } else {
                    *(float2*)((float*)Cv + ro) = cv;
                }
            }
        }
    }
}

// ---------------- bf16 mma.sync flash attention + cp.async K/V double buffering -----------
// Longest-first tile order: qt = gridDim.x-1-blockIdx.x (big blocks scheduled first).
#define AT_STRIDE 72

__global__ void __launch_bounds__(128) attn_bf16_kernel(
    const __nv_bfloat16* __restrict__ qkv, __nv_bfloat16* __restrict__ z)
{
    __shared__ __nv_bfloat16 qs[64][AT_STRIDE];
    __shared__ __nv_bfloat16 ks[2][64][AT_STRIDE];
    __shared__ __nv_bfloat16 vs[2][64][AT_STRIDE];

    int t    = threadIdx.x;
    int warp = t >> 5, lane = t & 31;
    int gr   = lane >> 2, gc = lane & 3;
    int sel  = lane >> 3, sl = lane & 7;
    int h    = blockIdx.y, b = blockIdx.z;
    int qt   = gridDim.x - 1 - blockIdx.x;
    int q0   = qt * 64;
    const __nv_bfloat16* base = qkv + (size_t)b * SEQ * QKVW;

    const float SCL = 0.18033688011112042f;

    uint32_t ksb[2] = { s2u(&ks[0][0][0]), s2u(&ks[1][0][0]) };
    uint32_t vsb[2] = { s2u(&vs[0][0][0]), s2u(&vs[1][0][0]) };

    #pragma unroll
    for (int i = 0; i < 4; i++) {
        int idx = t + i * 128;
        int row = idx >> 3, c8 = idx & 7;
        uint4 v = *(const uint4*)(base + (size_t)(q0 + row) * QKVW + h * DHEAD + c8 * 8);
        *(uint4*)&qs[row][c8 * 8] = v;
    }

    {
        #pragma unroll
        for (int i = 0; i < 4; i++) {
            int idx = t + i * 128;
            int row = idx >> 3, c8 = idx & 7;
            const __nv_bfloat16* rp = base + (size_t)row * QKVW + DMODEL + h * DHEAD + c8 * 8;
            asm volatile("cp.async.cg.shared.global [%0], [%1], 16;\n" ::
                "r"(ksb[0] + row * (AT_STRIDE * 2) + c8 * 16), "l"(rp));
            asm volatile("cp.async.cg.shared.global [%0], [%1], 16;\n" ::
                "r"(vsb[0] + row * (AT_STRIDE * 2) + c8 * 16), "l"(rp + DMODEL));
        }
        asm volatile("cp.async.commit_group;\n");
    }
    __syncthreads();

    int m0w = warp * 16;
    uint32_t qf[4][4];
    #pragma unroll
    for (int kd = 0; kd < 4; kd++) {
        uint32_t addr = s2u(&qs[m0w + (sel & 1) * 8 + sl][kd * 16 + (sel >> 1) * 8]);
        ldm_x4(qf[kd], addr);
    }

    float m_a = -INFINITY, m_b = -INFINITY, l_a = 0.f, l_b = 0.f;
    float oacc[8][4];
    #pragma unroll
    for (int ni = 0; ni < 8; ni++)
        #pragma unroll
        for (int i = 0; i < 4; i++) oacc[ni][i] = 0.f;

    int rq_a = q0 + m0w + gr;
    int rq_b = rq_a + 8;

    int nch = qt + 1;
    for (int c = 0; c < nch; c++) {
        int buf = c & 1;
        asm volatile("cp.async.wait_group 0;\n");
        __syncthreads();

        if (c + 1 < nch) {
            int k1 = (c + 1) * 64, nb = (c + 1) & 1;
            #pragma unroll
            for (int i = 0; i < 4; i++) {
                int idx = t + i * 128;
                int row = idx >> 3, c8 = idx & 7;
                const __nv_bfloat16* rp = base + (size_t)(k1 + row) * QKVW + DMODEL + h * DHEAD + c8 * 8;
                asm volatile("cp.async.cg.shared.global [%0], [%1], 16;\n" ::
                    "r"(ksb[nb] + row * (AT_STRIDE * 2) + c8 * 16), "l"(rp));
                asm volatile("cp.async.cg.shared.global [%0], [%1], 16;\n" ::
                    "r"(vsb[nb] + row * (AT_STRIDE * 2) + c8 * 16), "l"(rp + DMODEL));
            }
            asm volatile("cp.async.commit_group;\n");
        }

        int k0 = c * 64;
        float sacc[8][4];
        #pragma unroll
        for (int ni = 0; ni < 8; ni++)
            #pragma unroll
            for (int i = 0; i < 4; i++) sacc[ni][i] = 0.f;

        #pragma unroll
        for (int kd = 0; kd < 4; kd++) {
            #pragma unroll
            for (int nip = 0; nip < 4; nip++) {
                uint32_t kf[4];
                uint32_t addr = s2u(&ks[buf][nip * 16 + (sel >> 1) * 8 + sl][kd * 16 + (sel & 1) * 8]);
                ldm_x4(kf, addr);
                mma_bf16(sacc[2 * nip],     qf[kd], kf[0], kf[1]);
                mma_bf16(sacc[2 * nip + 1], qf[kd], kf[2], kf[3]);
            }
        }

        #pragma unroll
        for (int ni = 0; ni < 8; ni++)
            #pragma unroll
            for (int i = 0; i < 4; i++) sacc[ni][i] *= SCL;
        if (c == nch - 1) {
            #pragma unroll
            for (int ni = 0; ni < 8; ni++) {
                int j0 = k0 + ni * 8 + 2 * gc;
                if (j0     > rq_a) sacc[ni][0] = -INFINITY;
                if (j0 + 1 > rq_a) sacc[ni][1] = -INFINITY;
                if (j0     > rq_b) sacc[ni][2] = -INFINITY;
                if (j0 + 1 > rq_b) sacc[ni][3] = -INFINITY;
            }
        }

        float ra = -INFINITY, rb = -INFINITY;
        #pragma unroll
        for (int ni = 0; ni < 8; ni++) {
            ra = fmaxf(ra, fmaxf(sacc[ni][0], sacc[ni][1]));
            rb = fmaxf(rb, fmaxf(sacc[ni][2], sacc[ni][3]));
        }
        ra = fmaxf(ra, __shfl_xor_sync(0xffffffffu, ra, 1));
        ra = fmaxf(ra, __shfl_xor_sync(0xffffffffu, ra, 2));
        rb = fmaxf(rb, __shfl_xor_sync(0xffffffffu, rb, 1));
        rb = fmaxf(rb, __shfl_xor_sync(0xffffffffu, rb, 2));

        float na = fmaxf(m_a, ra), nb2 = fmaxf(m_b, rb);
        float ca = exp2f(m_a - na), cb = exp2f(m_b - nb2);
        m_a = na; m_b = nb2;
        l_a *= ca; l_b *= cb;

        uint32_t pf[4][4];
        #pragma unroll
        for (int ni = 0; ni < 8; ni++) {
            float p0 = exp2f(sacc[ni][0] - m_a);
            float p1 = exp2f(sacc[ni][1] - m_a);
            float p2 = exp2f(sacc[ni][2] - m_b);
            float p3 = exp2f(sacc[ni][3] - m_b);
            l_a += p0 + p1;
            l_b += p2 + p3;
            __nv_bfloat162 lo = __floats2bfloat162_rn(p0, p1);
            __nv_bfloat162 hi = __floats2bfloat162_rn(p2, p3);
            pf[ni >> 1][(ni & 1) * 2 + 0] = *(uint32_t*)&lo;
            pf[ni >> 1][(ni & 1) * 2 + 1] = *(uint32_t*)&hi;
        }
        #pragma unroll
        for (int ni = 0; ni < 8; ni++) {
            oacc[ni][0] *= ca; oacc[ni][1] *= ca;
            oacc[ni][2] *= cb; oacc[ni][3] *= cb;
        }

        #pragma unroll
        for (int kc = 0; kc < 4; kc++) {
            #pragma unroll
            for (int dp = 0; dp < 4; dp++) {
                uint32_t vf[4];
                uint32_t addr = s2u(&vs[buf][kc * 16 + (sel & 1) * 8 + sl][dp * 16 + (sel >> 1) * 8]);
                ldm_x4t(vf, addr);
                mma_bf16(oacc[2 * dp],     pf[kc], vf[0], vf[1]);
                mma_bf16(oacc[2 * dp + 1], pf[kc], vf[2], vf[3]);
            }
        }
    }

    l_a += __shfl_xor_sync(0xffffffffu, l_a, 1);
    l_a += __shfl_xor_sync(0xffffffffu, l_a, 2);
    l_b += __shfl_xor_sync(0xffffffffu, l_b, 1);
    l_b += __shfl_xor_sync(0xffffffffu, l_b, 2);
    float inva = 1.f / l_a, invb = 1.f / l_b;

    __nv_bfloat16* za  = z + (size_t)(b * SEQ + rq_a) * DMODEL + h * DHEAD;
    __nv_bfloat16* zbp = z + (size_t)(b * SEQ + rq_b) * DMODEL + h * DHEAD;
    #pragma unroll
    for (int ni = 0; ni < 8; ni++) {
        int col = ni * 8 + 2 * gc;
        __nv_bfloat162 oa = __floats2bfloat162_rn(oacc[ni][0] * inva, oacc[ni][1] * inva);
        __nv_bfloat162 ob = __floats2bfloat162_rn(oacc[ni][2] * invb, oacc[ni][3] * invb);
        *(__nv_bfloat162*)(za  + col) = oa;
        *(__nv_bfloat162*)(zbp + col) = ob;
    }
}

// ---------------------------------- launcher ---------------------------------------------
extern "C" void kernel_launch(void* const* d_in, const int* in_sizes, int n_in,
                              void* d_out, int out_size)
{
    (void)in_sizes; (void)n_in; (void)out_size;
    const float* resid = (const float*)d_in[0];
    const float* ln1w  = (const float*)d_in[1];
    const float* ln1b  = (const float*)d_in[2];
    const float* Wq    = (const float*)d_in[3];
    const float* bq    = (const float*)d_in[4];
    const float* Wk    = (const float*)d_in[5];
    const float* bk    = (const float*)d_in[6];
    const float* Wv    = (const float*)d_in[7];
    const float* bv    = (const float*)d_in[8];
    const float* Wo    = (const float*)d_in[9];
    const float* bo    = (const float*)d_in[10];
    const float* ln2w  = (const float*)d_in[11];
    const float* ln2b  = (const float*)d_in[12];
    const float* Win   = (const float*)d_in[13];
    const float* bin   = (const float*)d_in[14];
    const float* Wout  = (const float*)d_in[15];
    const float* bout  = (const float*)d_in[16];
    float* out = (float*)d_out;

    __nv_bfloat16 *xn, *wqkv, *qkv, *zb, *hid, *wo, *win, *wout;
    float *bqkv, *mid;
    cudaGetSymbolAddress((void**)&xn,   g_xn);
    cudaGetSymbolAddress((void**)&wqkv, g_wqkv);
    cudaGetSymbolAddress((void**)&bqkv, g_bqkv);
    cudaGetSymbolAddress((void**)&qkv,  g_qkv);
    cudaGetSymbolAddress((void**)&zb,   g_z);
    cudaGetSymbolAddress((void**)&mid,  g_mid);
    cudaGetSymbolAddress((void**)&hid,  g_hid);
    cudaGetSymbolAddress((void**)&wo,   g_wo);
    cudaGetSymbolAddress((void**)&win,  g_win);
    cudaGetSymbolAddress((void**)&wout, g_wout);

    // ---- fork side branches ----
    cudaEventRecord(g_hx.e0, 0);
    cudaStreamWaitEvent(g_hx.s1, g_hx.e0, 0);
    cudaStreamWaitEvent(g_hx.s2, g_hx.e0, 0);

    // branch 1: QKV bias copies + weight pack
    cudaMemcpyAsync(bqkv,        bq, DMODEL * sizeof(float), cudaMemcpyDeviceToDevice, g_hx.s1);
    cudaMemcpyAsync(bqkv + 1024, bk, DMODEL * sizeof(float), cudaMemcpyDeviceToDevice, g_hx.s1);
    cudaMemcpyAsync(bqkv + 2048, bv, DMODEL * sizeof(float), cudaMemcpyDeviceToDevice, g_hx.s1);
    pack_wqkv_kernel<<<(3 * DMODEL * DMODEL / 4) / 256, 256, 0, g_hx.s1>>>(Wq, Wk, Wv);
    cudaEventRecord(g_hx.e1, g_hx.s1);

    // branch 2: Wo/Win/Wout conversion
    conv_bf16_kernel<<<(DMODEL * DMODEL / 4 + 255) / 256, 256, 0, g_hx.s2>>>(
        (const float4*)Wo, (uint2*)wo, DMODEL * DMODEL / 4);
    conv_bf16_kernel<<<(DMODEL * DMLP / 4 + 255) / 256, 256, 0, g_hx.s2>>>(
        (const float4*)Win, (uint2*)win, DMODEL * DMLP / 4);
    conv_bf16_kernel<<<(DMLP * DMODEL / 4 + 255) / 256, 256, 0, g_hx.s2>>>(
        (const float4*)Wout, (uint2*)wout, DMLP * DMODEL / 4);
    cudaEventRecord(g_hx.e2, g_hx.s2);

    // main branch
    ln_kernel<<<NTOK, 256>>>(resid, ln1w, ln1b, xn);

    cudaStreamWaitEvent(0, g_hx.e1, 0);
    bgemm_kernel<false, false, true><<<dim3(QKVW / 128, NTOK / 128), 128>>>(
        xn, wqkv, bqkv, nullptr, qkv, NTOK, QKVW, DMODEL);

    attn_bf16_kernel<<<dim3(SEQ / 64, NHEADS, BATCH), 128>>>(qkv, zb);

    cudaStreamWaitEvent(0, g_hx.e2, 0);
    bgemm_kernel<false, true, false><<<dim3(DMODEL / 128, NTOK / 128), 128>>>(
        zb, wo, bo, resid, mid, NTOK, DMODEL, DMODEL);

    ln_kernel<<<NTOK, 256>>>(mid, ln2w, ln2b, xn);

    bgemm_kernel<true, false, true><<<dim3(DMLP / 128, NTOK / 128), 128>>>(
        xn, win, bin, nullptr, hid, NTOK, DMLP, DMODEL);

    bgemm_kernel<false, true, false><<<dim3(DMODEL / 128, NTOK / 128), 128>>>(
        hid, wout, bout, mid, out, NTOK, DMODEL, DMLP);
}

// round 17
// speedup vs baseline: 1.0861x; 1.0861x over previous
#include <cuda_runtime.h>
#include <cuda_bf16.h>
#include <math.h>
#include <stdint.h>

#define DMODEL 1024
#define NHEADS 16
#define DHEAD  64
#define DMLP   4096
#define BATCH  2
#define SEQ    2048
#define NTOK   (BATCH*SEQ)      /* 4096 */
#define QKVW   (3*DMODEL)       /* 3072 */
#define LNEPS  1e-5f

// ---------------- scratch (static device globals) ----------------------------------------
__device__ __nv_bfloat16 g_xn  [(size_t)NTOK*DMODEL];
__device__ __nv_bfloat16 g_wqkv[(size_t)DMODEL*QKVW];   // [K=1024][N=3072]
__device__ float         g_bqkv[QKVW];
__device__ __nv_bfloat16 g_qkv [(size_t)NTOK*QKVW];
__device__ __nv_bfloat16 g_z   [(size_t)NTOK*DMODEL];
__device__ float         g_mid [(size_t)NTOK*DMODEL];
__device__ __nv_bfloat16 g_hid [(size_t)NTOK*DMLP];
__device__ __nv_bfloat16 g_wo  [(size_t)DMODEL*DMODEL]; // [K][N]
__device__ __nv_bfloat16 g_win [(size_t)DMODEL*DMLP];   // [K][N]
__device__ __nv_bfloat16 g_wout[(size_t)DMLP*DMODEL];   // [K][N]

// ---------------- side streams for graph-parallel preamble (created pre-main) -------------
namespace {
struct HxStreams {
    cudaStream_t s1, s2;
    cudaEvent_t  e0, e1, e2;
    HxStreams() {
        cudaStreamCreateWithFlags(&s1, cudaStreamNonBlocking);
        cudaStreamCreateWithFlags(&s2, cudaStreamNonBlocking);
        cudaEventCreateWithFlags(&e0, cudaEventDisableTiming);
        cudaEventCreateWithFlags(&e1, cudaEventDisableTiming);
        cudaEventCreateWithFlags(&e2, cudaEventDisableTiming);
    }
};
HxStreams g_hx;
}

// ---------------- weight repack / convert -------------------------------------------------
// vectorized: one thread handles 4 consecutive k-elements (float4 -> 4x bf16)
__global__ void __launch_bounds__(256) pack_wqkv_kernel(
    const float* __restrict__ wq, const float* __restrict__ wk, const float* __restrict__ wv)
{
    int idx = blockIdx.x * 256 + threadIdx.x;          // [0, 3*1024*1024/4)
    int which = idx >> 18;
    int r4 = idx & 0x3FFFF;                            // 4-element chunk within one weight
    const float* src = (which == 0) ? wq : (which == 1) ? wk : wv;
    float4 v = *(const float4*)(src + (size_t)r4 * 4);
    int h  = r4 >> 14;
    int d  = (r4 >> 4) & 1023;
    int k0 = (r4 & 15) * 4;
    __nv_bfloat162 p0 = __floats2bfloat162_rn(v.x, v.y);
    __nv_bfloat162 p1 = __floats2bfloat162_rn(v.z, v.w);
    uint2 st;
    st.x = *(uint32_t*)&p0;
    st.y = *(uint32_t*)&p1;
    *(uint2*)(g_wqkv + (size_t)d * QKVW + which * DMODEL + h * DHEAD + k0) = st;
}

__global__ void __launch_bounds__(256) conv_bf16_kernel(
    const float4* __restrict__ s, uint2* __restrict__ d, int n4)
{
    int i = blockIdx.x * 256 + threadIdx.x;
    if (i < n4) {
        float4 v = s[i];
        __nv_bfloat162 a = __floats2bfloat162_rn(v.x, v.y);
        __nv_bfloat162 b = __floats2bfloat162_rn(v.z, v.w);
        uint2 o;
        o.x = *(uint32_t*)&a;
        o.y = *(uint32_t*)&b;
        d[i] = o;
    }
}

// ---------------- LayerNorm (fp32 in, bf16 out) -------------------------------------------
__global__ void __launch_bounds__(256) ln_kernel(
    const float* __restrict__ x, const float* __restrict__ w, const float* __restrict__ bb,
    __nv_bfloat16* __restrict__ y)
{
    __shared__ float red[18];
    int t = threadIdx.x;
    size_t off = (size_t)blockIdx.x * DMODEL;
    float4 v = *(const float4*)(x + off + t * 4);
    float s  = v.x + v.y + v.z + v.w;
    float sq = v.x*v.x + v.y*v.y + v.z*v.z + v.w*v.w;
    #pragma unroll
    for (int o = 16; o > 0; o >>= 1) {
        s  += __shfl_xor_sync(0xffffffffu, s,  o);
        sq += __shfl_xor_sync(0xffffffffu, sq, o);
    }
    if ((t & 31) == 0) { red[t >> 5] = s; red[8 + (t >> 5)] = sq; }
    __syncthreads();
    if (t == 0) {
        float ts = 0.f, tq = 0.f;
        #pragma unroll
        for (int i = 0; i < 8; i++) { ts += red[i]; tq += red[8 + i]; }
        float mean = ts * (1.f / DMODEL);
        float var  = tq * (1.f / DMODEL) - mean * mean;
        red[16] = mean;
        red[17] = rsqrtf(var + LNEPS);
    }
    __syncthreads();
    float mean = red[16], rstd = red[17];
    float4 w4 = *(const float4*)(w  + t * 4);
    float4 b4 = *(const float4*)(bb + t * 4);
    __nv_bfloat162 p0 = __floats2bfloat162_rn((v.x - mean) * rstd * w4.x + b4.x,
                                              (v.y - mean) * rstd * w4.y + b4.y);
    __nv_bfloat162 p1 = __floats2bfloat162_rn((v.z - mean) * rstd * w4.z + b4.z,
                                              (v.w - mean) * rstd * w4.w + b4.w);
    uint2 st;
    st.x = *(uint32_t*)&p0;
    st.y = *(uint32_t*)&p1;
    *(uint2*)(y + off + t * 4) = st;
}

// ---------------- common helpers ----------------------------------------------------------
__device__ __forceinline__ uint32_t s2u(const void* p) {
    return (uint32_t)__cvta_generic_to_shared(p);
}
__device__ __forceinline__ void mma_bf16(float* d, const uint32_t* a, uint32_t b0, uint32_t b1) {
    asm volatile(
        "mma.sync.aligned.m16n8k16.row.col.f32.bf16.bf16.f32 "
        "{%0,%1,%2,%3}, {%4,%5,%6,%7}, {%8,%9}, {%0,%1,%2,%3};\n"
        : "+f"(d[0]), "+f"(d[1]), "+f"(d[2]), "+f"(d[3])
        : "r"(a[0]), "r"(a[1]), "r"(a[2]), "r"(a[3]), "r"(b0), "r"(b1));
}
__device__ __forceinline__ void ldm_x4(uint32_t* r, uint32_t addr) {
    asm volatile("ldmatrix.sync.aligned.m8n8.x4.shared.b16 {%0,%1,%2,%3}, [%4];\n"
        : "=r"(r[0]), "=r"(r[1]), "=r"(r[2]), "=r"(r[3]) : "r"(addr));
}
__device__ __forceinline__ void ldm_x4t(uint32_t* r, uint32_t addr) {
    asm volatile("ldmatrix.sync.aligned.m8n8.x4.trans.shared.b16 {%0,%1,%2,%3}, [%4];\n"
        : "=r"(r[0]), "=r"(r[1]), "=r"(r[2]), "=r"(r[3]) : "r"(addr));
}

// ---------------- bf16 mma.sync GEMM: 4 warps, 64x64 warp tile, 4-stage, single-sync ------
// (launch bounds reverted to plain 128: round-15's (128,3) spilled the accumulators)
__device__ __forceinline__ int a_off(int m, int kbyte) {
    int line = m >> 1;
    return (line * 128 + (m & 1) * 64 + kbyte) ^ ((line & 7) << 4);
}
__device__ __forceinline__ int b_off(int k, int nbyte) {
    return (k * 256 + nbyte) ^ ((k & 7) << 4);
}

#define GSTAGES 4

template<bool RELU, bool RES, bool OUTBF>
__global__ void __launch_bounds__(128) bgemm_kernel(
    const __nv_bfloat16* __restrict__ A, const __nv_bfloat16* __restrict__ B,
    const float* __restrict__ bias, const float* __restrict__ Rp,
    void* __restrict__ Cv, int M, int N, int K)
{
    __shared__ __align__(128) unsigned char smem[GSTAGES * 16384];
    uint32_t base = s2u(smem);

    int tid  = threadIdx.x;
    int warp = tid >> 5, lane = tid & 31;
    int wm = warp >> 1, wn = warp & 1;
    int gr = lane >> 2, gc = lane & 3;

    const __nv_bfloat16* Ab = A + (size_t)blockIdx.y * 128 * K;
    const __nv_bfloat16* Bb = B + blockIdx.x * 128;

    int ar = tid >> 2, ac = tid & 3;
    int brr = tid >> 4, bcc = tid & 15;

    float acc[4][8][4];
    #pragma unroll
    for (int mi = 0; mi < 4; mi++)
        #pragma unroll
        for (int ni = 0; ni < 8; ni++)
            #pragma unroll
            for (int i = 0; i < 4; i++) acc[mi][ni][i] = 0.f;

    int T = K >> 5;

    #pragma unroll
    for (int s = 0; s < GSTAGES - 1; s++) {
        uint32_t as = base + s * 16384;
        uint32_t bs = as + 8192;
        int kt = s * 32;
        #pragma unroll
        for (int i = 0; i < 4; i++) {
            int r = ar + i * 32;
            asm volatile("cp.async.cg.shared.global [%0], [%1], 16;\n" ::
                "r"(as + a_off(r, ac * 16)), "l"(Ab + (size_t)r * K + kt + ac * 8));
        }
        #pragma unroll
        for (int i = 0; i < 4; i++) {
            int r = brr + i * 8;
            asm volatile("cp.async.cg.shared.global [%0], [%1], 16;\n" ::
                "r"(bs + b_off(r, bcc * 16)), "l"(Bb + (size_t)(kt + r) * N + bcc * 8));
        }
        asm volatile("cp.async.commit_group;\n");
    }

    for (int t = 0; t < T; t++) {
        asm volatile("cp.async.wait_group %0;\n" :: "n"(GSTAGES - 2));
        __syncthreads();

        if (t + GSTAGES - 1 < T) {
            int s  = (t + GSTAGES - 1) % GSTAGES;
            uint32_t was = base + s * 16384;
            uint32_t wbs = was + 8192;
            int kt = (t + GSTAGES - 1) * 32;
            #pragma unroll
            for (int i = 0; i < 4; i++) {
                int r = ar + i * 32;
                asm volatile("cp.async.cg.shared.global [%0], [%1], 16;\n" ::
                    "r"(was + a_off(r, ac * 16)), "l"(Ab + (size_t)r * K + kt + ac * 8));
            }
            #pragma unroll
            for (int i = 0; i < 4; i++) {
                int r = brr + i * 8;
                asm volatile("cp.async.cg.shared.global [%0], [%1], 16;\n" ::
                    "r"(wbs + b_off(r, bcc * 16)), "l"(Bb + (size_t)(kt + r) * N + bcc * 8));
            }
        }
        asm volatile("cp.async.commit_group;\n");

        uint32_t as = base + (t % GSTAGES) * 16384;
        uint32_t bs = as + 8192;

        #pragma unroll
        for (int ks = 0; ks < 2; ks++) {
            uint32_t af[4][4];
            #pragma unroll
            for (int mi = 0; mi < 4; mi++) {
                int m  = wm * 64 + mi * 16 + (lane & 15);
                int kb = ks * 32 + (lane >> 4) * 16;
                ldm_x4(af[mi], as + a_off(m, kb));
            }
            uint32_t bf[4][4];
            #pragma unroll
            for (int np = 0; np < 4; np++) {
                int k  = ks * 16 + (lane & 15);
                int nb = (wn * 64 + np * 16 + (lane >> 4) * 8) * 2;
                ldm_x4t(bf[np], bs + b_off(k, nb));
            }
            #pragma unroll
            for (int mi = 0; mi < 4; mi++)
                #pragma unroll
                for (int ni = 0; ni < 8; ni++)
                    mma_bf16(acc[mi][ni], af[mi], bf[ni >> 1][(ni & 1) * 2],
                             bf[ni >> 1][(ni & 1) * 2 + 1]);
        }
    }

    int Rm = blockIdx.y * 128 + wm * 64;
    int Rn = blockIdx.x * 128 + wn * 64;
    #pragma unroll
    for (int mi = 0; mi < 4; mi++) {
        #pragma unroll
        for (int ni = 0; ni < 8; ni++) {
            int col = Rn + ni * 8 + gc * 2;
            float2 bv = *(const float2*)&bias[col];
            #pragma unroll
            for (int hh = 0; hh < 2; hh++) {
                int row = Rm + mi * 16 + gr + hh * 8;
                size_t ro = (size_t)row * N + col;
                float2 cv;
                cv.x = acc[mi][ni][2 * hh + 0] + bv.x;
                cv.y = acc[mi][ni][2 * hh + 1] + bv.y;
                if (RES) {
                    float2 rv = *(const float2*)&Rp[ro];
                    cv.x += rv.x; cv.y += rv.y;
                }
                if (RELU) { cv.x = fmaxf(cv.x, 0.f); cv.y = fmaxf(cv.y, 0.f); }
                if (OUTBF) {
                    __nv_bfloat162 o = __floats2bfloat162_rn(cv.x, cv.y);
                    *(__nv_bfloat162*)((__nv_bfloat16*)Cv + ro) = o;
                } else {
                    *(float2*)((float*)Cv + ro) = cv;
                }
            }
        }
    }
}

// ---------------- bf16 mma.sync flash attention + cp.async K/V double buffering -----------
// Longest-first tile order: qt = gridDim.x-1-blockIdx.x (big blocks scheduled first).
#define AT_STRIDE 72

__global__ void __launch_bounds__(128) attn_bf16_kernel(
    const __nv_bfloat16* __restrict__ qkv, __nv_bfloat16* __restrict__ z)
{
    __shared__ __nv_bfloat16 qs[64][AT_STRIDE];
    __shared__ __nv_bfloat16 ks[2][64][AT_STRIDE];
    __shared__ __nv_bfloat16 vs[2][64][AT_STRIDE];

    int t    = threadIdx.x;
    int warp = t >> 5, lane = t & 31;
    int gr   = lane >> 2, gc = lane & 3;
    int sel  = lane >> 3, sl = lane & 7;
    int h    = blockIdx.y, b = blockIdx.z;
    int qt   = gridDim.x - 1 - blockIdx.x;
    int q0   = qt * 64;
    const __nv_bfloat16* base = qkv + (size_t)b * SEQ * QKVW;

    const float SCL = 0.18033688011112042f;

    uint32_t ksb[2] = { s2u(&ks[0][0][0]), s2u(&ks[1][0][0]) };
    uint32_t vsb[2] = { s2u(&vs[0][0][0]), s2u(&vs[1][0][0]) };

    #pragma unroll
    for (int i = 0; i < 4; i++) {
        int idx = t + i * 128;
        int row = idx >> 3, c8 = idx & 7;
        uint4 v = *(const uint4*)(base + (size_t)(q0 + row) * QKVW + h * DHEAD + c8 * 8);
        *(uint4*)&qs[row][c8 * 8] = v;
    }

    {
        #pragma unroll
        for (int i = 0; i < 4; i++) {
            int idx = t + i * 128;
            int row = idx >> 3, c8 = idx & 7;
            const __nv_bfloat16* rp = base + (size_t)row * QKVW + DMODEL + h * DHEAD + c8 * 8;
            asm volatile("cp.async.cg.shared.global [%0], [%1], 16;\n" ::
                "r"(ksb[0] + row * (AT_STRIDE * 2) + c8 * 16), "l"(rp));
            asm volatile("cp.async.cg.shared.global [%0], [%1], 16;\n" ::
                "r"(vsb[0] + row * (AT_STRIDE * 2) + c8 * 16), "l"(rp + DMODEL));
        }
        asm volatile("cp.async.commit_group;\n");
    }
    __syncthreads();

    int m0w = warp * 16;
    uint32_t qf[4][4];
    #pragma unroll
    for (int kd = 0; kd < 4; kd++) {
        uint32_t addr = s2u(&qs[m0w + (sel & 1) * 8 + sl][kd * 16 + (sel >> 1) * 8]);
        ldm_x4(qf[kd], addr);
    }

    float m_a = -INFINITY, m_b = -INFINITY, l_a = 0.f, l_b = 0.f;
    float oacc[8][4];
    #pragma unroll
    for (int ni = 0; ni < 8; ni++)
        #pragma unroll
        for (int i = 0; i < 4; i++) oacc[ni][i] = 0.f;

    int rq_a = q0 + m0w + gr;
    int rq_b = rq_a + 8;

    int nch = qt + 1;
    for (int c = 0; c < nch; c++) {
        int buf = c & 1;
        asm volatile("cp.async.wait_group 0;\n");
        __syncthreads();

        if (c + 1 < nch) {
            int k1 = (c + 1) * 64, nb = (c + 1) & 1;
            #pragma unroll
            for (int i = 0; i < 4; i++) {
                int idx = t + i * 128;
                int row = idx >> 3, c8 = idx & 7;
                const __nv_bfloat16* rp = base + (size_t)(k1 + row) * QKVW + DMODEL + h * DHEAD + c8 * 8;
                asm volatile("cp.async.cg.shared.global [%0], [%1], 16;\n" ::
                    "r"(ksb[nb] + row * (AT_STRIDE * 2) + c8 * 16), "l"(rp));
                asm volatile("cp.async.cg.shared.global [%0], [%1], 16;\n" ::
                    "r"(vsb[nb] + row * (AT_STRIDE * 2) + c8 * 16), "l"(rp + DMODEL));
            }
            asm volatile("cp.async.commit_group;\n");
        }

        int k0 = c * 64;
        float sacc[8][4];
        #pragma unroll
        for (int ni = 0; ni < 8; ni++)
            #pragma unroll
            for (int i = 0; i < 4; i++) sacc[ni][i] = 0.f;

        #pragma unroll
        for (int kd = 0; kd < 4; kd++) {
            #pragma unroll
            for (int nip = 0; nip < 4; nip++) {
                uint32_t kf[4];
                uint32_t addr = s2u(&ks[buf][nip * 16 + (sel >> 1) * 8 + sl][kd * 16 + (sel & 1) * 8]);
                ldm_x4(kf, addr);
                mma_bf16(sacc[2 * nip],     qf[kd], kf[0], kf[1]);
                mma_bf16(sacc[2 * nip + 1], qf[kd], kf[2], kf[3]);
            }
        }

        #pragma unroll
        for (int ni = 0; ni < 8; ni++)
            #pragma unroll
            for (int i = 0; i < 4; i++) sacc[ni][i] *= SCL;
        if (c == nch - 1) {
            #pragma unroll
            for (int ni = 0; ni < 8; ni++) {
                int j0 = k0 + ni * 8 + 2 * gc;
                if (j0     > rq_a) sacc[ni][0] = -INFINITY;
                if (j0 + 1 > rq_a) sacc[ni][1] = -INFINITY;
                if (j0     > rq_b) sacc[ni][2] = -INFINITY;
                if (j0 + 1 > rq_b) sacc[ni][3] = -INFINITY;
            }
        }

        float ra = -INFINITY, rb = -INFINITY;
        #pragma unroll
        for (int ni = 0; ni < 8; ni++) {
            ra = fmaxf(ra, fmaxf(sacc[ni][0], sacc[ni][1]));
            rb = fmaxf(rb, fmaxf(sacc[ni][2], sacc[ni][3]));
        }
        ra = fmaxf(ra, __shfl_xor_sync(0xffffffffu, ra, 1));
        ra = fmaxf(ra, __shfl_xor_sync(0xffffffffu, ra, 2));
        rb = fmaxf(rb, __shfl_xor_sync(0xffffffffu, rb, 1));
        rb = fmaxf(rb, __shfl_xor_sync(0xffffffffu, rb, 2));

        float na = fmaxf(m_a, ra), nb2 = fmaxf(m_b, rb);
        float ca = exp2f(m_a - na), cb = exp2f(m_b - nb2);
        m_a = na; m_b = nb2;
        l_a *= ca; l_b *= cb;

        uint32_t pf[4][4];
        #pragma unroll
        for (int ni = 0; ni < 8; ni++) {
            float p0 = exp2f(sacc[ni][0] - m_a);
            float p1 = exp2f(sacc[ni][1] - m_a);
            float p2 = exp2f(sacc[ni][2] - m_b);
            float p3 = exp2f(sacc[ni][3] - m_b);
            l_a += p0 + p1;
            l_b += p2 + p3;
            __nv_bfloat162 lo = __floats2bfloat162_rn(p0, p1);
            __nv_bfloat162 hi = __floats2bfloat162_rn(p2, p3);
            pf[ni >> 1][(ni & 1) * 2 + 0] = *(uint32_t*)&lo;
            pf[ni >> 1][(ni & 1) * 2 + 1] = *(uint32_t*)&hi;
        }
        #pragma unroll
        for (int ni = 0; ni < 8; ni++) {
            oacc[ni][0] *= ca; oacc[ni][1] *= ca;
            oacc[ni][2] *= cb; oacc[ni][3] *= cb;
        }

        #pragma unroll
        for (int kc = 0; kc < 4; kc++) {
            #pragma unroll
            for (int dp = 0; dp < 4; dp++) {
                uint32_t vf[4];
                uint32_t addr = s2u(&vs[buf][kc * 16 + (sel & 1) * 8 + sl][dp * 16 + (sel >> 1) * 8]);
                ldm_x4t(vf, addr);
                mma_bf16(oacc[2 * dp],     pf[kc], vf[0], vf[1]);
                mma_bf16(oacc[2 * dp + 1], pf[kc], vf[2], vf[3]);
            }
        }
    }

    l_a += __shfl_xor_sync(0xffffffffu, l_a, 1);
    l_a += __shfl_xor_sync(0xffffffffu, l_a, 2);
    l_b += __shfl_xor_sync(0xffffffffu, l_b, 1);
    l_b += __shfl_xor_sync(0xffffffffu, l_b, 2);
    float inva = 1.f / l_a, invb = 1.f / l_b;

    __nv_bfloat16* za  = z + (size_t)(b * SEQ + rq_a) * DMODEL + h * DHEAD;
    __nv_bfloat16* zbp = z + (size_t)(b * SEQ + rq_b) * DMODEL + h * DHEAD;
    #pragma unroll
    for (int ni = 0; ni < 8; ni++) {
        int col = ni * 8 + 2 * gc;
        __nv_bfloat162 oa = __floats2bfloat162_rn(oacc[ni][0] * inva, oacc[ni][1] * inva);
        __nv_bfloat162 ob = __floats2bfloat162_rn(oacc[ni][2] * invb, oacc[ni][3] * invb);
        *(__nv_bfloat162*)(za  + col) = oa;
        *(__nv_bfloat162*)(zbp + col) = ob;
    }
}

// ---------------------------------- launcher ---------------------------------------------
extern "C" void kernel_launch(void* const* d_in, const int* in_sizes, int n_in,
                              void* d_out, int out_size)
{
    (void)in_sizes; (void)n_in; (void)out_size;
    const float* resid = (const float*)d_in[0];
    const float* ln1w  = (const float*)d_in[1];
    const float* ln1b  = (const float*)d_in[2];
    const float* Wq    = (const float*)d_in[3];
    const float* bq    = (const float*)d_in[4];
    const float* Wk    = (const float*)d_in[5];
    const float* bk    = (const float*)d_in[6];
    const float* Wv    = (const float*)d_in[7];
    const float* bv    = (const float*)d_in[8];
    const float* Wo    = (const float*)d_in[9];
    const float* bo    = (const float*)d_in[10];
    const float* ln2w  = (const float*)d_in[11];
    const float* ln2b  = (const float*)d_in[12];
    const float* Win   = (const float*)d_in[13];
    const float* bin   = (const float*)d_in[14];
    const float* Wout  = (const float*)d_in[15];
    const float* bout  = (const float*)d_in[16];
    float* out = (float*)d_out;

    __nv_bfloat16 *xn, *wqkv, *qkv, *zb, *hid, *wo, *win, *wout;
    float *bqkv, *mid;
    cudaGetSymbolAddress((void**)&xn,   g_xn);
    cudaGetSymbolAddress((void**)&wqkv, g_wqkv);
    cudaGetSymbolAddress((void**)&bqkv, g_bqkv);
    cudaGetSymbolAddress((void**)&qkv,  g_qkv);
    cudaGetSymbolAddress((void**)&zb,   g_z);
    cudaGetSymbolAddress((void**)&mid,  g_mid);
    cudaGetSymbolAddress((void**)&hid,  g_hid);
    cudaGetSymbolAddress((void**)&wo,   g_wo);
    cudaGetSymbolAddress((void**)&win,  g_win);
    cudaGetSymbolAddress((void**)&wout, g_wout);

    // ---- fork side branches ----
    cudaEventRecord(g_hx.e0, 0);
    cudaStreamWaitEvent(g_hx.s1, g_hx.e0, 0);
    cudaStreamWaitEvent(g_hx.s2, g_hx.e0, 0);

    // branch 1: QKV bias copies + weight pack
    cudaMemcpyAsync(bqkv,        bq, DMODEL * sizeof(float), cudaMemcpyDeviceToDevice, g_hx.s1);
    cudaMemcpyAsync(bqkv + 1024, bk, DMODEL * sizeof(float), cudaMemcpyDeviceToDevice, g_hx.s1);
    cudaMemcpyAsync(bqkv + 2048, bv, DMODEL * sizeof(float), cudaMemcpyDeviceToDevice, g_hx.s1);
    pack_wqkv_kernel<<<(3 * DMODEL * DMODEL / 4) / 256, 256, 0, g_hx.s1>>>(Wq, Wk, Wv);
    cudaEventRecord(g_hx.e1, g_hx.s1);

    // branch 2: Wo/Win/Wout conversion
    conv_bf16_kernel<<<(DMODEL * DMODEL / 4 + 255) / 256, 256, 0, g_hx.s2>>>(
        (const float4*)Wo, (uint2*)wo, DMODEL * DMODEL / 4);
    conv_bf16_kernel<<<(DMODEL * DMLP / 4 + 255) / 256, 256, 0, g_hx.s2>>>(
        (const float4*)Win, (uint2*)win, DMODEL * DMLP / 4);
    conv_bf16_kernel<<<(DMLP * DMODEL / 4 + 255) / 256, 256, 0, g_hx.s2>>>(
        (const float4*)Wout, (uint2*)wout, DMLP * DMODEL / 4);
    cudaEventRecord(g_hx.e2, g_hx.s2);

    // main branch
    ln_kernel<<<NTOK, 256>>>(resid, ln1w, ln1b, xn);

    cudaStreamWaitEvent(0, g_hx.e1, 0);
    bgemm_kernel<false, false, true><<<dim3(QKVW / 128, NTOK / 128), 128>>>(
        xn, wqkv, bqkv, nullptr, qkv, NTOK, QKVW, DMODEL);

    attn_bf16_kernel<<<dim3(SEQ / 64, NHEADS, BATCH), 128>>>(qkv, zb);

    cudaStreamWaitEvent(0, g_hx.e2, 0);
    bgemm_kernel<false, true, false><<<dim3(DMODEL / 128, NTOK / 128), 128>>>(
        zb, wo, bo, resid, mid, NTOK, DMODEL, DMODEL);

    ln_kernel<<<NTOK, 256>>>(mid, ln2w, ln2b, xn);

    bgemm_kernel<true, false, true><<<dim3(DMLP / 128, NTOK / 128), 128>>>(
        xn, win, bin, nullptr, hid, NTOK, DMLP, DMODEL);

    bgemm_kernel<false, true, false><<<dim3(DMODEL / 128, NTOK / 128), 128>>>(
        hid, wout, bout, mid, out, NTOK, DMODEL, DMLP);
}